// round 1
// baseline (speedup 1.0000x reference)
#include <cuda_runtime.h>
#include <math.h>

#define BSZ    8
#define TT     1000
#define INDIM  256
#define DMODEL 512
#define FFDIM  2048
#define NLAYER 4
#define NHEAD  8
#define DHEAD  64
#define NCLS   8
#define MROWS  (BSZ*TT)   /* 8000 */

// ---------------- scratch (no cudaMalloc allowed) ----------------
__device__ float g_h   [MROWS * DMODEL];
__device__ float g_qkv [MROWS * 3 * DMODEL];
__device__ float g_ff  [MROWS * FFDIM];
__device__ float g_attn[MROWS * DMODEL];
__device__ float g_o   [MROWS * DMODEL];

// ---------------- generic SGEMM: C = A(MxK) * W(NxK)^T + bias, opt. ReLU ----
// BM=BN=128, BK=16, 256 threads, 8x8 microtile per thread.
__global__ __launch_bounds__(256)
void sgemm_bias_kernel(const float* __restrict__ A, const float* __restrict__ W,
                       const float* __restrict__ bias, float* __restrict__ Cmat,
                       int M, int N, int K, int relu)
{
    __shared__ float As[16][128];
    __shared__ float Bs[16][128];
    const int tid = threadIdx.x;
    const int m0 = blockIdx.x * 128;
    const int n0 = blockIdx.y * 128;
    const int ty = tid >> 4;    // 0..15
    const int tx = tid & 15;    // 0..15

    float acc[8][8];
#pragma unroll
    for (int i = 0; i < 8; i++)
#pragma unroll
        for (int j = 0; j < 8; j++) acc[i][j] = 0.f;

    const int lr = tid >> 2;        // 0..63
    const int lc = (tid & 3) << 2;  // 0,4,8,12

    for (int k0 = 0; k0 < K; k0 += 16) {
#pragma unroll
        for (int rr = 0; rr < 2; rr++) {
            int r = lr + rr * 64;
            int gr = m0 + r;
            float4 v = make_float4(0.f, 0.f, 0.f, 0.f);
            if (gr < M) v = *(const float4*)(A + (size_t)gr * K + k0 + lc);
            As[lc + 0][r] = v.x; As[lc + 1][r] = v.y;
            As[lc + 2][r] = v.z; As[lc + 3][r] = v.w;
        }
#pragma unroll
        for (int rr = 0; rr < 2; rr++) {
            int r = lr + rr * 64;
            int gn = n0 + r;  // N is always a multiple of 128 here
            float4 v = *(const float4*)(W + (size_t)gn * K + k0 + lc);
            Bs[lc + 0][r] = v.x; Bs[lc + 1][r] = v.y;
            Bs[lc + 2][r] = v.z; Bs[lc + 3][r] = v.w;
        }
        __syncthreads();
#pragma unroll
        for (int kk = 0; kk < 16; kk++) {
            float a[8], b[8];
#pragma unroll
            for (int i = 0; i < 8; i++) a[i] = As[kk][ty * 8 + i];
#pragma unroll
            for (int j = 0; j < 8; j++) b[j] = Bs[kk][tx * 8 + j];
#pragma unroll
            for (int i = 0; i < 8; i++)
#pragma unroll
                for (int j = 0; j < 8; j++)
                    acc[i][j] = fmaf(a[i], b[j], acc[i][j]);
        }
        __syncthreads();
    }

#pragma unroll
    for (int i = 0; i < 8; i++) {
        int gr = m0 + ty * 8 + i;
        if (gr >= M) continue;
#pragma unroll
        for (int j = 0; j < 8; j += 4) {
            int gc = n0 + tx * 8 + j;
            float4 v;
            v.x = acc[i][j + 0] + bias[gc + 0];
            v.y = acc[i][j + 1] + bias[gc + 1];
            v.z = acc[i][j + 2] + bias[gc + 2];
            v.w = acc[i][j + 3] + bias[gc + 3];
            if (relu) {
                v.x = fmaxf(v.x, 0.f); v.y = fmaxf(v.y, 0.f);
                v.z = fmaxf(v.z, 0.f); v.w = fmaxf(v.w, 0.f);
            }
            *(float4*)(Cmat + (size_t)gr * N + gc) = v;
        }
    }
}

// ---------------- sinusoidal positional encoding add ----------------
__global__ void pe_add_kernel(float* __restrict__ h)
{
    int idx = blockIdx.x * blockDim.x + threadIdx.x;
    if (idx >= MROWS * DMODEL) return;
    int d = idx & (DMODEL - 1);
    int t = (idx >> 9) % TT;
    int dd = d & ~1;
    // div = exp(dd * (-ln(10000)/512))
    float div = expf((float)dd * (-9.210340371976184f / 512.0f));
    float ang = (float)t * div;
    h[idx] += (d & 1) ? cosf(ang) : sinf(ang);
}

// ---------------- banded flash attention ----------------
// grid: (ceil(T/128), H, BS); 128 threads; 1 thread = 1 query.
__global__ __launch_bounds__(128)
void attn_kernel(const float* __restrict__ qkv, float* __restrict__ out)
{
    __shared__ float Ks[32][64];
    __shared__ float Vs[32][64];
    __shared__ float Sc[128][33];

    const int b  = blockIdx.z;
    const int hh = blockIdx.y;
    const int q0 = blockIdx.x * 128;
    const int tid = threadIdx.x;
    const int tq = q0 + tid;
    const bool active = (tq < TT);
    const int w = 25 * (hh + 1);

    float qreg[64];
    {
        const float* qp = qkv + ((size_t)(b * TT) + (active ? tq : 0)) * 1536 + hh * 64;
#pragma unroll
        for (int d = 0; d < 64; d += 4) {
            float4 v = *(const float4*)(qp + d);
            qreg[d] = v.x; qreg[d + 1] = v.y; qreg[d + 2] = v.z; qreg[d + 3] = v.w;
        }
    }
    float acc[64];
#pragma unroll
    for (int d = 0; d < 64; d++) acc[d] = 0.f;
    float mrun = -INFINITY, lsum = 0.f;

    int kstart = q0 - w;       if (kstart < 0) kstart = 0;
    int kend   = q0 + 127 + w; if (kend > TT - 1) kend = TT - 1;

    for (int j0 = kstart; j0 <= kend; j0 += 32) {
        int tl = kend - j0 + 1; if (tl > 32) tl = 32;
        __syncthreads();
        // load 32x64 K and V tiles
        for (int it = tid; it < 32 * 16; it += 128) {
            int r = it >> 4;
            int c = (it & 15) << 2;
            float4 kv = make_float4(0.f, 0.f, 0.f, 0.f);
            float4 vv = make_float4(0.f, 0.f, 0.f, 0.f);
            if (r < tl) {
                const float* base = qkv + ((size_t)(b * TT) + j0 + r) * 1536 + hh * 64 + c;
                kv = *(const float4*)(base + 512);
                vv = *(const float4*)(base + 1024);
            }
            *(float4*)&Ks[r][c] = kv;
            *(float4*)&Vs[r][c] = vv;
        }
        __syncthreads();

        float mt = -INFINITY;
#pragma unroll 4
        for (int jj = 0; jj < 32; jj++) {
            float s = 0.f;
#pragma unroll
            for (int d = 0; d < 64; d++) s = fmaf(qreg[d], Ks[jj][d], s);
            s *= 0.125f;
            int j = j0 + jj;
            int dist = tq - j; dist = dist < 0 ? -dist : dist;
            bool valid = active && (jj < tl) && (dist <= w);
            s = valid ? s : -INFINITY;
            Sc[tid][jj] = s;
            mt = fmaxf(mt, s);
        }
        if (mt > -INFINITY) {
            float mnew = fmaxf(mrun, mt);
            float alpha = __expf(mrun - mnew);   // mrun=-inf -> 0
            lsum *= alpha;
#pragma unroll
            for (int d = 0; d < 64; d++) acc[d] *= alpha;
#pragma unroll 2
            for (int jj = 0; jj < 32; jj++) {
                float p = __expf(Sc[tid][jj] - mnew);  // masked -> exp(-inf)=0
                lsum += p;
#pragma unroll
                for (int d = 0; d < 64; d++) acc[d] = fmaf(p, Vs[jj][d], acc[d]);
            }
            mrun = mnew;
        }
    }

    if (active) {
        float inv = 1.0f / lsum;
        float* op = out + ((size_t)(b * TT) + tq) * DMODEL + hh * 64;
#pragma unroll
        for (int d = 0; d < 64; d += 4) {
            float4 v = make_float4(acc[d] * inv, acc[d + 1] * inv,
                                   acc[d + 2] * inv, acc[d + 3] * inv);
            *(float4*)(op + d) = v;
        }
    }
}

// ---------------- residual + LayerNorm (in place into h) ----------------
__global__ __launch_bounds__(256)
void resln_kernel(float* __restrict__ h, const float* __restrict__ o,
                  const float* __restrict__ g, const float* __restrict__ be)
{
    const int row = blockIdx.x;
    const int tid = threadIdx.x;
    const size_t base = (size_t)row * DMODEL;
    float x0 = h[base + tid] + o[base + tid];
    float x1 = h[base + tid + 256] + o[base + tid + 256];
    float s  = x0 + x1;
    float sq = x0 * x0 + x1 * x1;

    __shared__ float ss[8], sqs[8];
#pragma unroll
    for (int off = 16; off > 0; off >>= 1) {
        s  += __shfl_down_sync(0xffffffffu, s, off);
        sq += __shfl_down_sync(0xffffffffu, sq, off);
    }
    int wid = tid >> 5, lane = tid & 31;
    if (lane == 0) { ss[wid] = s; sqs[wid] = sq; }
    __syncthreads();
    if (tid == 0) {
        float st = 0.f, sqt = 0.f;
        for (int i = 0; i < 8; i++) { st += ss[i]; sqt += sqs[i]; }
        ss[0] = st; sqs[0] = sqt;
    }
    __syncthreads();
    float mean = ss[0] * (1.0f / 512.0f);
    float var  = sqs[0] * (1.0f / 512.0f) - mean * mean;
    float r = rsqrtf(var + 1e-5f);
    h[base + tid]       = (x0 - mean) * r * g[tid] + be[tid];
    h[base + tid + 256] = (x1 - mean) * r * g[tid + 256] + be[tid + 256];
}

// ---------------- max-pool over time + classifier + log_softmax ----------
__global__ __launch_bounds__(512)
void pool_cls_kernel(const float* __restrict__ h, const float* __restrict__ Wcls,
                     const float* __restrict__ bcls, float* __restrict__ out)
{
    const int b = blockIdx.x;
    const int tid = threadIdx.x; // 512
    float mx = -INFINITY;
    for (int t = 0; t < TT; t++)
        mx = fmaxf(mx, h[((size_t)b * TT + t) * DMODEL + tid]);
    __shared__ float sp[DMODEL];
    __shared__ float logits[NCLS];
    sp[tid] = mx;
    __syncthreads();
    if (tid < NCLS) {
        float s = bcls[tid];
        for (int d = 0; d < DMODEL; d++) s += Wcls[tid * DMODEL + d] * sp[d];
        logits[tid] = s;
    }
    __syncthreads();
    if (tid == 0) {
        float m = -INFINITY;
        for (int c = 0; c < NCLS; c++) m = fmaxf(m, logits[c]);
        float se = 0.f;
        for (int c = 0; c < NCLS; c++) se += expf(logits[c] - m);
        float lse = m + logf(se);
        for (int c = 0; c < NCLS; c++) out[b * NCLS + c] = logits[c] - lse;
    }
}

// ---------------- launch ----------------
extern "C" void kernel_launch(void* const* d_in, const int* in_sizes, int n_in,
                              void* d_out, int out_size)
{
    const float* x    = (const float*)d_in[0];
    const float* Wemb = (const float*)d_in[1];
    const float* bemb = (const float*)d_in[2];
    const float* Wqkv = (const float*)d_in[3];
    const float* bqkv = (const float*)d_in[4];
    const float* Wo   = (const float*)d_in[5];
    const float* bo   = (const float*)d_in[6];
    const float* W1   = (const float*)d_in[7];
    const float* b1f  = (const float*)d_in[8];
    const float* W2   = (const float*)d_in[9];
    const float* b2f  = (const float*)d_in[10];
    const float* g1   = (const float*)d_in[11];
    const float* be1  = (const float*)d_in[12];
    const float* g2   = (const float*)d_in[13];
    const float* be2  = (const float*)d_in[14];
    const float* Wcls = (const float*)d_in[15];
    const float* bcls = (const float*)d_in[16];

    float *h, *qkv, *ff, *attn, *o;
    cudaGetSymbolAddress((void**)&h,    g_h);
    cudaGetSymbolAddress((void**)&qkv,  g_qkv);
    cudaGetSymbolAddress((void**)&ff,   g_ff);
    cudaGetSymbolAddress((void**)&attn, g_attn);
    cudaGetSymbolAddress((void**)&o,    g_o);

    const int GM = (MROWS + 127) / 128;  // 63

    // embedding + PE
    sgemm_bias_kernel<<<dim3(GM, DMODEL / 128), 256>>>(x, Wemb, bemb, h,
                                                       MROWS, DMODEL, INDIM, 0);
    pe_add_kernel<<<(MROWS * DMODEL + 255) / 256, 256>>>(h);

    for (int l = 0; l < NLAYER; l++) {
        const float* wq = Wqkv + (size_t)l * 3 * DMODEL * DMODEL;
        const float* bq = bqkv + (size_t)l * 3 * DMODEL;
        sgemm_bias_kernel<<<dim3(GM, (3 * DMODEL) / 128), 256>>>(h, wq, bq, qkv,
                                                MROWS, 3 * DMODEL, DMODEL, 0);

        attn_kernel<<<dim3((TT + 127) / 128, NHEAD, BSZ), 128>>>(qkv, attn);

        sgemm_bias_kernel<<<dim3(GM, DMODEL / 128), 256>>>(attn,
                Wo + (size_t)l * DMODEL * DMODEL, bo + (size_t)l * DMODEL, o,
                MROWS, DMODEL, DMODEL, 0);

        resln_kernel<<<MROWS, 256>>>(h, o, g1 + (size_t)l * DMODEL,
                                     be1 + (size_t)l * DMODEL);

        sgemm_bias_kernel<<<dim3(GM, FFDIM / 128), 256>>>(h,
                W1 + (size_t)l * FFDIM * DMODEL, b1f + (size_t)l * FFDIM, ff,
                MROWS, FFDIM, DMODEL, 1);

        sgemm_bias_kernel<<<dim3(GM, DMODEL / 128), 256>>>(ff,
                W2 + (size_t)l * DMODEL * FFDIM, b2f + (size_t)l * DMODEL, o,
                MROWS, DMODEL, FFDIM, 0);

        resln_kernel<<<MROWS, 256>>>(h, o, g2 + (size_t)l * DMODEL,
                                     be2 + (size_t)l * DMODEL);
    }

    pool_cls_kernel<<<BSZ, 512>>>(h, Wcls, bcls, (float*)d_out);
}

// round 3
// speedup vs baseline: 3.0103x; 3.0103x over previous
#include <cuda_runtime.h>
#include <cuda_fp16.h>
#include <math.h>
#include <stdint.h>

#define BSZ    8
#define TT     1000
#define INDIM  256
#define DMODEL 512
#define FFDIM  2048
#define NLAYER 4
#define NHEAD  8
#define DHEAD  64
#define NCLS   8
#define MROWS  (BSZ*TT)   /* 8000 */

// ---------------- scratch (no cudaMalloc allowed) ----------------
__device__ float  g_h   [MROWS * DMODEL];
__device__ float  g_qkv [MROWS * 3 * DMODEL];
__device__ float  g_o   [MROWS * DMODEL];

__device__ __half g_x16   [MROWS * INDIM];
__device__ __half g_h16   [MROWS * DMODEL];
__device__ __half g_attn16[MROWS * DMODEL];
__device__ __half g_ff16  [MROWS * FFDIM];

__device__ __half g_w16emb[DMODEL * INDIM];
__device__ __half g_w16qkv[NLAYER * 3 * DMODEL * DMODEL];
__device__ __half g_w16o  [NLAYER * DMODEL * DMODEL];
__device__ __half g_w16f1 [NLAYER * FFDIM * DMODEL];
__device__ __half g_w16f2 [NLAYER * DMODEL * FFDIM];

// ======================= helpers =======================
__device__ __forceinline__ uint32_t smem_u32(const void* p) {
    return (uint32_t)__cvta_generic_to_shared(p);
}
__device__ __forceinline__ uint32_t lds_b32(uint32_t a) {
    uint32_t v;
    asm volatile("ld.shared.b32 %0, [%1];" : "=r"(v) : "r"(a));
    return v;
}
#define CP_ASYNC16(dst, src, pb) \
    asm volatile("cp.async.cg.shared.global [%0], [%1], 16, %2;\n" \
                 :: "r"(dst), "l"(src), "r"(pb))
#define CP_COMMIT() asm volatile("cp.async.commit_group;\n" ::: "memory")
#define CP_WAIT(n)  asm volatile("cp.async.wait_group %0;\n" :: "n"(n) : "memory")

__device__ __forceinline__ void mma16816(float c[4], uint32_t a0, uint32_t a1,
                                         uint32_t a2, uint32_t a3,
                                         uint32_t b0, uint32_t b1) {
    asm volatile(
        "mma.sync.aligned.m16n8k16.row.col.f32.f16.f16.f32 "
        "{%0,%1,%2,%3}, {%4,%5,%6,%7}, {%8,%9}, {%0,%1,%2,%3};"
        : "+f"(c[0]), "+f"(c[1]), "+f"(c[2]), "+f"(c[3])
        : "r"(a0), "r"(a1), "r"(a2), "r"(a3), "r"(b0), "r"(b1));
}

// ======================= fp16 HMMA GEMM =======================
// C(MxN) = A16(MxK) * W16(NxK)^T + bias(fp32); flags: 1=relu, 2=fp16 out.
// 128x128x32 tiles, 3-stage cp.async, 256 threads, warp grid 2(m) x 4(n),
// warp tile 64x32. Smem rows padded to 112B (56 halves): conflict-free.
#define PADK 56
#define STAGE_BYTES (128 * PADK * 2)      /* 14336 */
#define HG_SMEM (6 * STAGE_BYTES)         /* 84 KB: 3 stages x (A,B) */

__global__ __launch_bounds__(256)
void hgemm_kernel(const __half* __restrict__ A, const __half* __restrict__ W,
                  const float* __restrict__ bias, void* __restrict__ Cout,
                  int M, int N, int K, int flags)
{
    extern __shared__ char smem[];
    const uint32_t sA = smem_u32(smem);                      // 3 stages
    const uint32_t sB = sA + 3 * STAGE_BYTES;                // 3 stages

    const int tid  = threadIdx.x;
    const int wid  = tid >> 5;
    const int lane = tid & 31;
    const int wm = wid >> 2;        // 0..1
    const int wn = wid & 3;         // 0..3
    const int g   = lane >> 2;      // 0..7
    const int tig = lane & 3;       // 0..3
    const int m0 = blockIdx.x * 128;
    const int n0 = blockIdx.y * 128;

    const int nt = K >> 5;          // K/32, always >= 8 here

    // ---- tile loader: tile t into slot s ----
    auto load_tile = [&](int t, int s) {
        const uint32_t da = sA + s * STAGE_BYTES;
        const uint32_t db = sB + s * STAGE_BYTES;
        const __half* Ak = A + t * 32;
        const __half* Wk = W + t * 32;
#pragma unroll
        for (int it = 0; it < 2; it++) {
            int id  = tid + it * 256;       // 0..511
            int row = id >> 2;              // 0..127
            int c   = id & 3;               // 16B chunk
            // A (guard M)
            int ar = m0 + row; int arc = ar < M ? ar : (M - 1);
            int pa = (ar < M) ? 16 : 0;
            CP_ASYNC16(da + row * 112 + c * 16,
                       (const char*)(Ak + (size_t)arc * K) + c * 16, pa);
            // B (N multiple of 128)
            CP_ASYNC16(db + row * 112 + c * 16,
                       (const char*)(Wk + (size_t)(n0 + row) * K) + c * 16, 16);
        }
        CP_COMMIT();
    };

    float acc[4][4][4];
#pragma unroll
    for (int i = 0; i < 4; i++)
#pragma unroll
        for (int j = 0; j < 4; j++)
#pragma unroll
            for (int r = 0; r < 4; r++) acc[i][j][r] = 0.f;

    load_tile(0, 0);
    load_tile(1, 1);

    for (int kt = 0; kt < nt; kt++) {
        if (kt + 2 < nt) load_tile(kt + 2, (kt + 2) % 3);

        if (kt + 2 < nt)      { CP_WAIT(2); }
        else if (kt + 1 < nt) { CP_WAIT(1); }
        else                  { CP_WAIT(0); }
        __syncthreads();

        const int s = kt % 3;
        const uint32_t baseA = sA + s * STAGE_BYTES;
        const uint32_t baseB = sB + s * STAGE_BYTES;

#pragma unroll
        for (int ks = 0; ks < 2; ks++) {
            const int kk = ks * 16;
            uint32_t bf[4][2];
#pragma unroll
            for (int ni = 0; ni < 4; ni++) {
                uint32_t ba = baseB + (uint32_t)(wn * 32 + ni * 8 + g) * 112
                                    + (uint32_t)(kk + 2 * tig) * 2;
                bf[ni][0] = lds_b32(ba);
                bf[ni][1] = lds_b32(ba + 16);
            }
#pragma unroll
            for (int mi = 0; mi < 4; mi++) {
                uint32_t aa = baseA + (uint32_t)(wm * 64 + mi * 16 + g) * 112
                                    + (uint32_t)(kk + 2 * tig) * 2;
                uint32_t a0 = lds_b32(aa);
                uint32_t a1 = lds_b32(aa + 8 * 112);
                uint32_t a2 = lds_b32(aa + 16);
                uint32_t a3 = lds_b32(aa + 8 * 112 + 16);
#pragma unroll
                for (int ni = 0; ni < 4; ni++)
                    mma16816(acc[mi][ni], a0, a1, a2, a3, bf[ni][0], bf[ni][1]);
            }
        }
        __syncthreads();
    }

    // ---- epilogue ----
    const int relu  = flags & 1;
    const int out16 = flags & 2;
    float* Cf = (float*)Cout;
    __half* Ch = (__half*)Cout;
#pragma unroll
    for (int mi = 0; mi < 4; mi++) {
        int gr0 = m0 + wm * 64 + mi * 16 + g;
#pragma unroll
        for (int ni = 0; ni < 4; ni++) {
            int gc = n0 + wn * 32 + ni * 8 + 2 * tig;
            float b0 = bias[gc], b1 = bias[gc + 1];
            float v0 = acc[mi][ni][0] + b0;
            float v1 = acc[mi][ni][1] + b1;
            float v2 = acc[mi][ni][2] + b0;
            float v3 = acc[mi][ni][3] + b1;
            if (relu) {
                v0 = fmaxf(v0, 0.f); v1 = fmaxf(v1, 0.f);
                v2 = fmaxf(v2, 0.f); v3 = fmaxf(v3, 0.f);
            }
            if (gr0 < M) {
                if (out16) *(__half2*)(Ch + (size_t)gr0 * N + gc) = __floats2half2_rn(v0, v1);
                else       *(float2*)(Cf + (size_t)gr0 * N + gc) = make_float2(v0, v1);
            }
            if (gr0 + 8 < M) {
                if (out16) *(__half2*)(Ch + (size_t)(gr0 + 8) * N + gc) = __floats2half2_rn(v2, v3);
                else       *(float2*)(Cf + (size_t)(gr0 + 8) * N + gc) = make_float2(v2, v3);
            }
        }
    }
}

// ---------------- f32 -> f16 convert ----------------
__global__ void cvt_kernel(const float* __restrict__ s, __half* __restrict__ d, int n)
{
    int i = (blockIdx.x * blockDim.x + threadIdx.x) * 4;
    if (i >= n) return;
    float4 v = *(const float4*)(s + i);
    *(__half2*)(d + i)     = __floats2half2_rn(v.x, v.y);
    *(__half2*)(d + i + 2) = __floats2half2_rn(v.z, v.w);
}

// ---------------- PE add (writes fp32 h and fp16 h16) ----------------
__global__ void pe_add_kernel(float* __restrict__ h, __half* __restrict__ h16)
{
    int idx = blockIdx.x * blockDim.x + threadIdx.x;
    if (idx >= MROWS * DMODEL) return;
    int d = idx & (DMODEL - 1);
    int t = (idx >> 9) % TT;
    int dd = d & ~1;
    float div = expf((float)dd * (-9.210340371976184f / 512.0f));
    float ang = (float)t * div;
    float v = h[idx] + ((d & 1) ? cosf(ang) : sinf(ang));
    h[idx] = v;
    h16[idx] = __float2half(v);
}

// ---------------- banded flash attention (fp16 output) ----------------
__global__ __launch_bounds__(128)
void attn_kernel(const float* __restrict__ qkv, __half* __restrict__ out)
{
    __shared__ float Ks[32][64];
    __shared__ float Vs[32][64];
    __shared__ float Sc[128][33];

    const int b  = blockIdx.z;
    const int hh = blockIdx.y;
    const int q0 = blockIdx.x * 128;
    const int tid = threadIdx.x;
    const int tq = q0 + tid;
    const bool active = (tq < TT);
    const int w = 25 * (hh + 1);

    float qreg[64];
    {
        const float* qp = qkv + ((size_t)(b * TT) + (active ? tq : 0)) * 1536 + hh * 64;
#pragma unroll
        for (int d = 0; d < 64; d += 4) {
            float4 v = *(const float4*)(qp + d);
            qreg[d] = v.x; qreg[d + 1] = v.y; qreg[d + 2] = v.z; qreg[d + 3] = v.w;
        }
    }
    float acc[64];
#pragma unroll
    for (int d = 0; d < 64; d++) acc[d] = 0.f;
    float mrun = -INFINITY, lsum = 0.f;

    int kstart = q0 - w;       if (kstart < 0) kstart = 0;
    int kend   = q0 + 127 + w; if (kend > TT - 1) kend = TT - 1;

    for (int j0 = kstart; j0 <= kend; j0 += 32) {
        int tl = kend - j0 + 1; if (tl > 32) tl = 32;
        __syncthreads();
        for (int it = tid; it < 32 * 16; it += 128) {
            int r = it >> 4;
            int c = (it & 15) << 2;
            float4 kv = make_float4(0.f, 0.f, 0.f, 0.f);
            float4 vv = make_float4(0.f, 0.f, 0.f, 0.f);
            if (r < tl) {
                const float* base = qkv + ((size_t)(b * TT) + j0 + r) * 1536 + hh * 64 + c;
                kv = *(const float4*)(base + 512);
                vv = *(const float4*)(base + 1024);
            }
            *(float4*)&Ks[r][c] = kv;
            *(float4*)&Vs[r][c] = vv;
        }
        __syncthreads();

        float mt = -INFINITY;
#pragma unroll 4
        for (int jj = 0; jj < 32; jj++) {
            float s = 0.f;
#pragma unroll
            for (int d = 0; d < 64; d++) s = fmaf(qreg[d], Ks[jj][d], s);
            s *= 0.125f;
            int j = j0 + jj;
            int dist = tq - j; dist = dist < 0 ? -dist : dist;
            bool valid = active && (jj < tl) && (dist <= w);
            s = valid ? s : -INFINITY;
            Sc[tid][jj] = s;
            mt = fmaxf(mt, s);
        }
        if (mt > -INFINITY) {
            float mnew = fmaxf(mrun, mt);
            float alpha = __expf(mrun - mnew);
            lsum *= alpha;
#pragma unroll
            for (int d = 0; d < 64; d++) acc[d] *= alpha;
#pragma unroll 2
            for (int jj = 0; jj < 32; jj++) {
                float p = __expf(Sc[tid][jj] - mnew);
                lsum += p;
#pragma unroll
                for (int d = 0; d < 64; d++) acc[d] = fmaf(p, Vs[jj][d], acc[d]);
            }
            mrun = mnew;
        }
    }

    if (active) {
        float inv = 1.0f / lsum;
        __half* op = out + ((size_t)(b * TT) + tq) * DMODEL + hh * 64;
#pragma unroll
        for (int d = 0; d < 64; d += 2)
            *(__half2*)(op + d) = __floats2half2_rn(acc[d] * inv, acc[d + 1] * inv);
    }
}

// ---------------- residual + LayerNorm (fp32 h + fp16 h16) ----------------
__global__ __launch_bounds__(256)
void resln_kernel(float* __restrict__ h, const float* __restrict__ o,
                  const float* __restrict__ g, const float* __restrict__ be,
                  __half* __restrict__ h16)
{
    const int row = blockIdx.x;
    const int tid = threadIdx.x;
    const size_t base = (size_t)row * DMODEL;
    float x0 = h[base + tid] + o[base + tid];
    float x1 = h[base + tid + 256] + o[base + tid + 256];
    float s  = x0 + x1;
    float sq = x0 * x0 + x1 * x1;

    __shared__ float ss[8], sqs[8];
#pragma unroll
    for (int off = 16; off > 0; off >>= 1) {
        s  += __shfl_down_sync(0xffffffffu, s, off);
        sq += __shfl_down_sync(0xffffffffu, sq, off);
    }
    int wid = tid >> 5, lane = tid & 31;
    if (lane == 0) { ss[wid] = s; sqs[wid] = sq; }
    __syncthreads();
    if (tid == 0) {
        float st = 0.f, sqt = 0.f;
        for (int i = 0; i < 8; i++) { st += ss[i]; sqt += sqs[i]; }
        ss[0] = st; sqs[0] = sqt;
    }
    __syncthreads();
    float mean = ss[0] * (1.0f / 512.0f);
    float var  = sqs[0] * (1.0f / 512.0f) - mean * mean;
    float r = rsqrtf(var + 1e-5f);
    float y0 = (x0 - mean) * r * g[tid] + be[tid];
    float y1 = (x1 - mean) * r * g[tid + 256] + be[tid + 256];
    h[base + tid]       = y0;
    h[base + tid + 256] = y1;
    h16[base + tid]       = __float2half(y0);
    h16[base + tid + 256] = __float2half(y1);
}

// ---------------- max-pool + classifier + log_softmax ----------
__global__ __launch_bounds__(512)
void pool_cls_kernel(const float* __restrict__ h, const float* __restrict__ Wcls,
                     const float* __restrict__ bcls, float* __restrict__ out)
{
    const int b = blockIdx.x;
    const int tid = threadIdx.x;
    float mx = -INFINITY;
    for (int t = 0; t < TT; t++)
        mx = fmaxf(mx, h[((size_t)b * TT + t) * DMODEL + tid]);
    __shared__ float sp[DMODEL];
    __shared__ float logits[NCLS];
    sp[tid] = mx;
    __syncthreads();
    if (tid < NCLS) {
        float s = bcls[tid];
        for (int d = 0; d < DMODEL; d++) s += Wcls[tid * DMODEL + d] * sp[d];
        logits[tid] = s;
    }
    __syncthreads();
    if (tid == 0) {
        float m = -INFINITY;
        for (int c = 0; c < NCLS; c++) m = fmaxf(m, logits[c]);
        float se = 0.f;
        for (int c = 0; c < NCLS; c++) se += expf(logits[c] - m);
        float lse = m + logf(se);
        for (int c = 0; c < NCLS; c++) out[b * NCLS + c] = logits[c] - lse;
    }
}

// ---------------- launch ----------------
extern "C" void kernel_launch(void* const* d_in, const int* in_sizes, int n_in,
                              void* d_out, int out_size)
{
    const float* x    = (const float*)d_in[0];
    const float* Wemb = (const float*)d_in[1];
    const float* bemb = (const float*)d_in[2];
    const float* Wqkv = (const float*)d_in[3];
    const float* bqkv = (const float*)d_in[4];
    const float* Wo   = (const float*)d_in[5];
    const float* bo   = (const float*)d_in[6];
    const float* W1   = (const float*)d_in[7];
    const float* b1f  = (const float*)d_in[8];
    const float* W2   = (const float*)d_in[9];
    const float* b2f  = (const float*)d_in[10];
    const float* g1   = (const float*)d_in[11];
    const float* be1  = (const float*)d_in[12];
    const float* g2   = (const float*)d_in[13];
    const float* be2  = (const float*)d_in[14];
    const float* Wcls = (const float*)d_in[15];
    const float* bcls = (const float*)d_in[16];

    float *h, *qkv, *o;
    __half *x16, *h16, *attn16, *ff16, *wemb16, *wqkv16, *wo16, *wf1, *wf2;
    cudaGetSymbolAddress((void**)&h,     g_h);
    cudaGetSymbolAddress((void**)&qkv,   g_qkv);
    cudaGetSymbolAddress((void**)&o,     g_o);
    cudaGetSymbolAddress((void**)&x16,   g_x16);
    cudaGetSymbolAddress((void**)&h16,   g_h16);
    cudaGetSymbolAddress((void**)&attn16,g_attn16);
    cudaGetSymbolAddress((void**)&ff16,  g_ff16);
    cudaGetSymbolAddress((void**)&wemb16,g_w16emb);
    cudaGetSymbolAddress((void**)&wqkv16,g_w16qkv);
    cudaGetSymbolAddress((void**)&wo16,  g_w16o);
    cudaGetSymbolAddress((void**)&wf1,   g_w16f1);
    cudaGetSymbolAddress((void**)&wf2,   g_w16f2);

    cudaFuncSetAttribute(hgemm_kernel,
                         cudaFuncAttributeMaxDynamicSharedMemorySize, HG_SMEM);

    auto cvt = [&](const float* s, __half* d, int n) {
        cvt_kernel<<<(n / 4 + 255) / 256, 256>>>(s, d, n);
    };
    cvt(x,    x16,    MROWS * INDIM);
    cvt(Wemb, wemb16, DMODEL * INDIM);
    cvt(Wqkv, wqkv16, NLAYER * 3 * DMODEL * DMODEL);
    cvt(Wo,   wo16,   NLAYER * DMODEL * DMODEL);
    cvt(W1,   wf1,    NLAYER * FFDIM * DMODEL);
    cvt(W2,   wf2,    NLAYER * DMODEL * FFDIM);

    const int GM = (MROWS + 127) / 128;  // 63

    // embedding + PE
    hgemm_kernel<<<dim3(GM, DMODEL / 128), 256, HG_SMEM>>>(
        x16, wemb16, bemb, h, MROWS, DMODEL, INDIM, 0);
    pe_add_kernel<<<(MROWS * DMODEL + 255) / 256, 256>>>(h, h16);

    for (int l = 0; l < NLAYER; l++) {
        hgemm_kernel<<<dim3(GM, (3 * DMODEL) / 128), 256, HG_SMEM>>>(
            h16, wqkv16 + (size_t)l * 3 * DMODEL * DMODEL,
            bqkv + (size_t)l * 3 * DMODEL, qkv, MROWS, 3 * DMODEL, DMODEL, 0);

        attn_kernel<<<dim3((TT + 127) / 128, NHEAD, BSZ), 128>>>(qkv, attn16);

        hgemm_kernel<<<dim3(GM, DMODEL / 128), 256, HG_SMEM>>>(
            attn16, wo16 + (size_t)l * DMODEL * DMODEL,
            bo + (size_t)l * DMODEL, o, MROWS, DMODEL, DMODEL, 0);

        resln_kernel<<<MROWS, 256>>>(h, o, g1 + (size_t)l * DMODEL,
                                     be1 + (size_t)l * DMODEL, h16);

        hgemm_kernel<<<dim3(GM, FFDIM / 128), 256, HG_SMEM>>>(
            h16, wf1 + (size_t)l * FFDIM * DMODEL,
            b1f + (size_t)l * FFDIM, ff16, MROWS, FFDIM, DMODEL, 1 | 2);

        hgemm_kernel<<<dim3(GM, DMODEL / 128), 256, HG_SMEM>>>(
            ff16, wf2 + (size_t)l * DMODEL * FFDIM,
            b2f + (size_t)l * DMODEL, o, MROWS, DMODEL, FFDIM, 0);

        resln_kernel<<<MROWS, 256>>>(h, o, g2 + (size_t)l * DMODEL,
                                     be2 + (size_t)l * DMODEL, h16);
    }

    pool_cls_kernel<<<BSZ, 512>>>(h, Wcls, bcls, (float*)d_out);
}